// round 9
// baseline (speedup 1.0000x reference)
#include <cuda_runtime.h>
#include <cuda_bf16.h>
#include <float.h>

#define N_BINS 15
#define NUM_CLS 1000
#define NUM_SEG (NUM_CLS * N_BINS)   // 15000, divisible by 4

// Scratch: per-(class,bin) signed accumulation of (conf - acc).
// Zero-initialized at module load; the reduce kernel re-zeroes it after
// consuming it, so every graph replay starts from zeros.
__device__ float g_seg[NUM_SEG];

// TWO warps per row (500 elems = 4 float4/lane): halves data registers
// (16 vs 32) -> ~8 blocks/SM (100% occ vs 72%), halves per-warp compute
// chain. Softmax state stays lane-local until the warp merge; the two
// half-row partials combine via a 3-word smem exchange.
// Dtype probe inlined: warps ballot on the high 32-bit words of the first
// 32 would-be int64 labels (one hot L2 line). int64 labels in [0,1000)
// have all-zero high words; int32 all-zero prob = (1/1000)^32.
__global__ __launch_bounds__(256)
void ecce_main_kernel(const float* __restrict__ logits,
                      const void* __restrict__ labels,
                      int N, int C) {
    int wid  = threadIdx.x >> 5;          // 0..7
    int lane = threadIdx.x & 31;
    int gw   = blockIdx.x * 8 + wid;      // global warp id
    int row  = gw >> 1;                   // 2 warps per row
    int half = gw & 1;

    // ---- inline dtype probe (all warps agree; single hot line) ----
    int nprobe = min(32, N >> 1);
    int nz = 0;
    if (lane < nprobe) nz = ((const int*)labels)[2 * lane + 1];
    unsigned any = __ballot_sync(0xFFFFFFFFu, nz != 0);
    bool lab64 = (any == 0);

    float m = -FLT_MAX;
    float s = 0.0f;
    int   idx = 0x7FFFFFFF;

    if (row < N) {
        if (C == 1000) {
            // ---- specialized path: 125 float4 per half-row, 4/lane ----
            const float4* rp = reinterpret_cast<const float4*>(
                logits + (size_t)row * 1000 + half * 500);
            const float4 pad = make_float4(-FLT_MAX, -FLT_MAX, -FLT_MAX, -FLT_MAX);
            float4 v[4];
            #pragma unroll
            for (int k = 0; k < 4; k++) {
                int i = lane + (k << 5);
                v[k] = (i < 125) ? rp[i] : pad;
            }
            int goff = half * 500;
            // Phase A: lane-local max + argmax (first occurrence).
            #pragma unroll
            for (int k = 0; k < 4; k++) {
                int base = goff + ((lane + (k << 5)) << 2);
                #pragma unroll
                for (int e = 0; e < 4; e++) {
                    float x = (e == 0) ? v[k].x : (e == 1) ? v[k].y : (e == 2) ? v[k].z : v[k].w;
                    if (x > m) { m = x; idx = base + e; }
                }
            }
            // Phase B: un-rescaled exp-sum vs lane-local max (pads -> 0).
            #pragma unroll
            for (int k = 0; k < 4; k++) {
                s += __expf(v[k].x - m) + __expf(v[k].y - m)
                   + __expf(v[k].z - m) + __expf(v[k].w - m);
            }
        } else {
            // ---- generic fallback: online softmax over this warp's half ----
            const float* rp = logits + (size_t)row * C;
            int startc = half * (C >> 1);
            int endc   = half ? C : (C >> 1);
            for (int i = startc + lane; i < endc; i += 32) {
                float x = rp[i];
                if (x > m) {
                    s = s * __expf(m - x) + 1.0f;
                    m = x; idx = i;
                } else {
                    s += __expf(x - m);
                }
            }
        }

        // Warp merge of (m, idx, s); tie-break toward lower index.
        #pragma unroll
        for (int off = 16; off > 0; off >>= 1) {
            float m2 = __shfl_down_sync(0xFFFFFFFFu, m, off);
            float s2 = __shfl_down_sync(0xFFFFFFFFu, s, off);
            int   i2 = __shfl_down_sync(0xFFFFFFFFu, idx, off);
            if (m2 > m || (m2 == m && i2 < idx)) {
                s = s * __expf(m - m2) + s2;
                m = m2; idx = i2;
            } else {
                s += s2 * __expf(m2 - m);
            }
        }
    }

    // ---- combine the two half-row partials via shared memory ----
    __shared__ float sm_m[8], sm_s[8];
    __shared__ int   sm_i[8];
    if (lane == 0) { sm_m[wid] = m; sm_s[wid] = s; sm_i[wid] = idx; }
    __syncthreads();

    if (half == 0 && lane == 0 && row < N) {
        float m0 = sm_m[wid],     s0 = sm_s[wid];     int i0 = sm_i[wid];
        float m1 = sm_m[wid + 1], s1 = sm_s[wid + 1]; int i1 = sm_i[wid + 1];
        float M, S; int I;
        if (m1 > m0 || (m1 == m0 && i1 < i0)) {
            M = m1; S = s1 + s0 * __expf(m0 - m1); I = i1;
        } else {
            M = m0; S = s0 + s1 * __expf(m1 - m0); I = i0;
        }
        (void)M;
        float conf = 1.0f / S;   // = exp(max-max)/sum(exp(l - max))
        int bin = (int)ceilf(conf * (float)N_BINS) - 1;
        bin = min(max(bin, 0), N_BINS - 1);
        int lab;
        if (lab64) lab = (int)((const long long*)labels)[row];
        else       lab = ((const int*)labels)[row];
        lab = min(max(lab, 0), NUM_CLS - 1);  // defensive
        float acc = (I == lab) ? 1.0f : 0.0f;
        atomicAdd(&g_seg[lab * N_BINS + bin], conf - acc);
    }
}

// Single-block reduction: ecce = sum(|seg|) / N, and re-zero g_seg for the
// next graph replay. float4 loads/stores, 1024 threads (MLP-rich).
__global__ __launch_bounds__(1024)
void ecce_reduce_kernel(float* __restrict__ out, int N) {
    __shared__ float sh[32];
    float4* p = reinterpret_cast<float4*>(g_seg);
    const float4 zero4 = make_float4(0.f, 0.f, 0.f, 0.f);

    float acc = 0.0f;
    #pragma unroll 4
    for (int i = threadIdx.x; i < NUM_SEG / 4; i += 1024) {
        float4 v = p[i];
        acc += fabsf(v.x) + fabsf(v.y) + fabsf(v.z) + fabsf(v.w);
        p[i] = zero4;  // restore zero invariant
    }

    #pragma unroll
    for (int off = 16; off > 0; off >>= 1)
        acc += __shfl_xor_sync(0xFFFFFFFFu, acc, off);
    int wid = threadIdx.x >> 5, lane = threadIdx.x & 31;
    if (lane == 0) sh[wid] = acc;
    __syncthreads();
    if (wid == 0) {
        acc = sh[lane];
        #pragma unroll
        for (int off = 16; off > 0; off >>= 1)
            acc += __shfl_xor_sync(0xFFFFFFFFu, acc, off);
        if (lane == 0) out[0] = acc / (float)N;
    }
}

extern "C" void kernel_launch(void* const* d_in, const int* in_sizes, int n_in,
                              void* d_out, int out_size) {
    // Logits is the (much) larger input; don't assume ordering.
    int i_logits = (in_sizes[0] >= in_sizes[1]) ? 0 : 1;
    int i_labels = 1 - i_logits;

    const float* logits = (const float*)d_in[i_logits];
    const void*  labels = d_in[i_labels];
    float*       out    = (float*)d_out;

    int N = in_sizes[i_labels];           // 131072
    int C = in_sizes[i_logits] / N;       // 1000

    // 2 warps per row, 8 warps per block -> 4 rows per block.
    int blocks = (N + 3) / 4;
    ecce_main_kernel<<<blocks, 256>>>(logits, labels, N, C);

    ecce_reduce_kernel<<<1, 1024>>>(out, N);
}

// round 10
// speedup vs baseline: 1.3084x; 1.3084x over previous
#include <cuda_runtime.h>
#include <cuda_bf16.h>
#include <float.h>

#define N_BINS 15
#define NUM_CLS 1000
#define NUM_SEG (NUM_CLS * N_BINS)   // 15000, divisible by 4

// Scratch: per-(class,bin) signed accumulation of (conf - acc).
// Zero-initialized at module load; the reduce kernel re-zeroes it after
// consuming it, so every graph replay starts from zeros.
__device__ float g_seg[NUM_SEG];

// One warp per row (R7 backbone) with NO argmax index tracking:
//   accuracy = (logits[row][label] == rowmax)
// (exact-equality; a tie between the label and an earlier argmax has
// probability ~0 for continuous float32 inputs). Phase A is a pure FMNMX
// tree -> the predicated ALU chains that kept issue at 67% are gone.
// Dtype probe inlined: warps ballot on the high 32-bit words of the first
// 32 would-be int64 labels (one hot L2 line). int64 labels in [0,1000)
// have all-zero high words; int32 all-zero prob = (1/1000)^32.
__global__ __launch_bounds__(256)
void ecce_main_kernel(const float* __restrict__ logits,
                      const void* __restrict__ labels,
                      int N, int C) {
    int warp = (blockIdx.x * blockDim.x + threadIdx.x) >> 5;
    int lane = threadIdx.x & 31;
    if (warp >= N) return;

    // ---- inline dtype probe (all warps agree; single hot line) ----
    int nprobe = min(32, N >> 1);
    int nz = 0;
    if (lane < nprobe) nz = ((const int*)labels)[2 * lane + 1];
    unsigned any = __ballot_sync(0xFFFFFFFFu, nz != 0);
    bool lab64 = (any == 0);

    // Hoist the label load (lane 0) so it overlaps the row loads.
    int lab = 0;
    if (lane == 0) {
        if (lab64) lab = (int)((const long long*)labels)[warp];
        else       lab = ((const int*)labels)[warp];
        lab = min(max(lab, 0), NUM_CLS - 1);  // defensive
    }

    const float* row_f = logits + (size_t)warp * C;
    const float4* row = reinterpret_cast<const float4*>(row_f);
    const int nvec = C >> 2;

    float m = -FLT_MAX;
    float s = 0.0f;

    if (nvec == 250) {
        // ---- specialized C=1000 path: front-batch 8x LDG.128 per lane ----
        const float4 pad = make_float4(-FLT_MAX, -FLT_MAX, -FLT_MAX, -FLT_MAX);
        float4 v[8];
        #pragma unroll
        for (int k = 0; k < 8; k++) {
            int i = lane + (k << 5);
            v[k] = (i < 250) ? row[i] : pad;
        }
        // Phase A: lane-local max, pure FMNMX tree (no index, no predicates).
        #pragma unroll
        for (int k = 0; k < 8; k++)
            m = fmaxf(m, fmaxf(fmaxf(v[k].x, v[k].y), fmaxf(v[k].z, v[k].w)));
        // Phase B: un-rescaled exp-sum vs lane-local max (pads -> exp(-inf)=0).
        #pragma unroll
        for (int k = 0; k < 8; k++) {
            s += __expf(v[k].x - m) + __expf(v[k].y - m)
               + __expf(v[k].z - m) + __expf(v[k].w - m);
        }
    } else {
        // ---- generic fallback: online max+sum, no index ----
        for (int i = lane; i < nvec; i += 32) {
            float4 v = row[i];
            #pragma unroll
            for (int e = 0; e < 4; e++) {
                float x = (e == 0) ? v.x : (e == 1) ? v.y : (e == 2) ? v.z : v.w;
                if (x > m) {
                    s = s * __expf(m - x) + 1.0f;
                    m = x;
                } else {
                    s += __expf(x - m);
                }
            }
        }
    }

    // Warp merge of (m, s): max + rescaled sum (no index compares).
    #pragma unroll
    for (int off = 16; off > 0; off >>= 1) {
        float m2 = __shfl_down_sync(0xFFFFFFFFu, m, off);
        float s2 = __shfl_down_sync(0xFFFFFFFFu, s, off);
        float mn = fmaxf(m, m2);
        s = s * __expf(m - mn) + s2 * __expf(m2 - mn);
        m = mn;
    }

    if (lane == 0) {
        float conf = 1.0f / s;             // = exp(max-max)/sum(exp(l-max))
        int bin = (int)ceilf(conf * (float)N_BINS) - 1;
        bin = min(max(bin, 0), N_BINS - 1);
        float x_lab = row_f[lab];          // L1-hot: row was just streamed
        float acc = (x_lab == m) ? 1.0f : 0.0f;
        atomicAdd(&g_seg[lab * N_BINS + bin], conf - acc);
    }
}

// Single-block reduction: ecce = sum(|seg|) / N, and re-zero g_seg for the
// next graph replay. float4 loads/stores, 1024 threads (MLP-rich).
__global__ __launch_bounds__(1024)
void ecce_reduce_kernel(float* __restrict__ out, int N) {
    __shared__ float sh[32];
    float4* p = reinterpret_cast<float4*>(g_seg);
    const float4 zero4 = make_float4(0.f, 0.f, 0.f, 0.f);

    float acc = 0.0f;
    #pragma unroll 4
    for (int i = threadIdx.x; i < NUM_SEG / 4; i += 1024) {
        float4 v = p[i];
        acc += fabsf(v.x) + fabsf(v.y) + fabsf(v.z) + fabsf(v.w);
        p[i] = zero4;  // restore zero invariant
    }

    #pragma unroll
    for (int off = 16; off > 0; off >>= 1)
        acc += __shfl_xor_sync(0xFFFFFFFFu, acc, off);
    int wid = threadIdx.x >> 5, lane = threadIdx.x & 31;
    if (lane == 0) sh[wid] = acc;
    __syncthreads();
    if (wid == 0) {
        acc = sh[lane];
        #pragma unroll
        for (int off = 16; off > 0; off >>= 1)
            acc += __shfl_xor_sync(0xFFFFFFFFu, acc, off);
        if (lane == 0) out[0] = acc / (float)N;
    }
}

extern "C" void kernel_launch(void* const* d_in, const int* in_sizes, int n_in,
                              void* d_out, int out_size) {
    // Logits is the (much) larger input; don't assume ordering.
    int i_logits = (in_sizes[0] >= in_sizes[1]) ? 0 : 1;
    int i_labels = 1 - i_logits;

    const float* logits = (const float*)d_in[i_logits];
    const void*  labels = d_in[i_labels];
    float*       out    = (float*)d_out;

    int N = in_sizes[i_labels];           // 131072
    int C = in_sizes[i_logits] / N;       // 1000

    int warps_per_block = 256 / 32;       // 8 rows per block
    int blocks = (N + warps_per_block - 1) / warps_per_block;
    ecce_main_kernel<<<blocks, 256>>>(logits, labels, N, C);

    ecce_reduce_kernel<<<1, 1024>>>(out, N);
}

// round 11
// speedup vs baseline: 1.3233x; 1.0114x over previous
#include <cuda_runtime.h>
#include <cuda_bf16.h>
#include <float.h>

#define N_BINS 15
#define NUM_CLS 1000
#define NUM_SEG (NUM_CLS * N_BINS)   // 15000, divisible by 4

// Scratch: per-(class,bin) signed accumulation of (conf - acc).
// Zero-initialized at module load; the reduce kernel re-zeroes it after
// consuming it, so every graph replay starts from zeros.
__device__ float g_seg[NUM_SEG];

// One warp per row (R10 backbone — measured ~78.7us, ~6.7 TB/s) with NO
// argmax index tracking: accuracy = (logits[row][label] == rowmax).
// Dtype probe inlined: warps ballot on the high 32-bit words of the first
// 32 would-be int64 labels (one hot L2 line). int64 labels in [0,1000)
// have all-zero high words; int32 all-zero prob = (1/1000)^32.
__global__ __launch_bounds__(256)
void ecce_main_kernel(const float* __restrict__ logits,
                      const void* __restrict__ labels,
                      int N, int C) {
    int warp = (blockIdx.x * blockDim.x + threadIdx.x) >> 5;
    int lane = threadIdx.x & 31;
    if (warp >= N) return;

    // ---- inline dtype probe (all warps agree; single hot line) ----
    int nprobe = min(32, N >> 1);
    int nz = 0;
    if (lane < nprobe) nz = ((const int*)labels)[2 * lane + 1];
    unsigned any = __ballot_sync(0xFFFFFFFFu, nz != 0);
    bool lab64 = (any == 0);

    // Hoist the label load (lane 0) so it overlaps the row loads.
    int lab = 0;
    if (lane == 0) {
        if (lab64) lab = (int)((const long long*)labels)[warp];
        else       lab = ((const int*)labels)[warp];
        lab = min(max(lab, 0), NUM_CLS - 1);  // defensive
    }

    const float* row_f = logits + (size_t)warp * C;
    const float4* row = reinterpret_cast<const float4*>(row_f);
    const int nvec = C >> 2;

    float m = -FLT_MAX;
    float s = 0.0f;

    if (nvec == 250) {
        // ---- specialized C=1000 path: front-batch 8x LDG.128 per lane ----
        const float4 pad = make_float4(-FLT_MAX, -FLT_MAX, -FLT_MAX, -FLT_MAX);
        float4 v[8];
        #pragma unroll
        for (int k = 0; k < 8; k++) {
            int i = lane + (k << 5);
            v[k] = (i < 250) ? row[i] : pad;
        }
        // Phase A: lane-local max, pure FMNMX tree (no index, no predicates).
        #pragma unroll
        for (int k = 0; k < 8; k++)
            m = fmaxf(m, fmaxf(fmaxf(v[k].x, v[k].y), fmaxf(v[k].z, v[k].w)));
        // Phase B: un-rescaled exp-sum vs lane-local max (pads -> exp(-inf)=0).
        #pragma unroll
        for (int k = 0; k < 8; k++) {
            s += __expf(v[k].x - m) + __expf(v[k].y - m)
               + __expf(v[k].z - m) + __expf(v[k].w - m);
        }
    } else {
        // ---- generic fallback: online max+sum, no index ----
        for (int i = lane; i < nvec; i += 32) {
            float4 v = row[i];
            #pragma unroll
            for (int e = 0; e < 4; e++) {
                float x = (e == 0) ? v.x : (e == 1) ? v.y : (e == 2) ? v.z : v.w;
                if (x > m) {
                    s = s * __expf(m - x) + 1.0f;
                    m = x;
                } else {
                    s += __expf(x - m);
                }
            }
        }
    }

    // Warp merge of (m, s): max + rescaled sum (no index compares).
    #pragma unroll
    for (int off = 16; off > 0; off >>= 1) {
        float m2 = __shfl_down_sync(0xFFFFFFFFu, m, off);
        float s2 = __shfl_down_sync(0xFFFFFFFFu, s, off);
        float mn = fmaxf(m, m2);
        s = s * __expf(m - mn) + s2 * __expf(m2 - mn);
        m = mn;
    }

    if (lane == 0) {
        float conf = 1.0f / s;             // = exp(max-max)/sum(exp(l-max))
        int bin = (int)ceilf(conf * (float)N_BINS) - 1;
        bin = min(max(bin, 0), N_BINS - 1);
        float x_lab = row_f[lab];          // L1-hot: row was just streamed
        float acc = (x_lab == m) ? 1.0f : 0.0f;
        atomicAdd(&g_seg[lab * N_BINS + bin], conf - acc);
    }
}

// Single-block reduction: ecce = sum(|seg|) / N, and re-zero g_seg for the
// next graph replay. Launched with PDL: its launch/prologue overlaps the
// main kernel's tail wave; cudaGridDependencySynchronize() guarantees the
// main grid's atomics are complete and visible before g_seg is read.
__global__ __launch_bounds__(1024)
void ecce_reduce_kernel(float* __restrict__ out, int N) {
    cudaGridDependencySynchronize();       // wait for main grid completion

    __shared__ float sh[32];
    float4* p = reinterpret_cast<float4*>(g_seg);
    const float4 zero4 = make_float4(0.f, 0.f, 0.f, 0.f);

    float acc = 0.0f;
    #pragma unroll 4
    for (int i = threadIdx.x; i < NUM_SEG / 4; i += 1024) {
        float4 v = p[i];
        acc += fabsf(v.x) + fabsf(v.y) + fabsf(v.z) + fabsf(v.w);
        p[i] = zero4;  // restore zero invariant
    }

    #pragma unroll
    for (int off = 16; off > 0; off >>= 1)
        acc += __shfl_xor_sync(0xFFFFFFFFu, acc, off);
    int wid = threadIdx.x >> 5, lane = threadIdx.x & 31;
    if (lane == 0) sh[wid] = acc;
    __syncthreads();
    if (wid == 0) {
        acc = sh[lane];
        #pragma unroll
        for (int off = 16; off > 0; off >>= 1)
            acc += __shfl_xor_sync(0xFFFFFFFFu, acc, off);
        if (lane == 0) out[0] = acc / (float)N;
    }
}

extern "C" void kernel_launch(void* const* d_in, const int* in_sizes, int n_in,
                              void* d_out, int out_size) {
    // Logits is the (much) larger input; don't assume ordering.
    int i_logits = (in_sizes[0] >= in_sizes[1]) ? 0 : 1;
    int i_labels = 1 - i_logits;

    const float* logits = (const float*)d_in[i_logits];
    const void*  labels = d_in[i_labels];
    float*       out    = (float*)d_out;

    int N = in_sizes[i_labels];           // 131072
    int C = in_sizes[i_logits] / N;       // 1000

    int warps_per_block = 256 / 32;       // 8 rows per block
    int blocks = (N + warps_per_block - 1) / warps_per_block;
    ecce_main_kernel<<<blocks, 256>>>(logits, labels, N, C);

    // PDL launch of the reduce: overlap its launch with main's tail.
    cudaLaunchConfig_t cfg = {};
    cfg.gridDim  = dim3(1, 1, 1);
    cfg.blockDim = dim3(1024, 1, 1);
    cfg.dynamicSmemBytes = 0;
    cfg.stream = 0;  // legacy default stream (the capture stream)
    cudaLaunchAttribute attrs[1];
    attrs[0].id = cudaLaunchAttributeProgrammaticStreamSerialization;
    attrs[0].val.programmaticStreamSerializationAllowed = 1;
    cfg.attrs = attrs;
    cfg.numAttrs = 1;
    cudaLaunchKernelEx(&cfg, ecce_reduce_kernel, out, N);
}

// round 12
// speedup vs baseline: 1.3548x; 1.0238x over previous
#include <cuda_runtime.h>
#include <cuda_bf16.h>
#include <float.h>

#define N_BINS 15
#define NUM_CLS 1000
#define NUM_SEG (NUM_CLS * N_BINS)   // 15000, divisible by 4

// Scratch: per-(class,bin) signed accumulation of (conf - acc).
// Zero-initialized at module load; the reduce kernel re-zeroes it after
// consuming it, so every graph replay starts from zeros.
__device__ float g_seg[NUM_SEG];

// One warp per row, no argmax index tracking:
//   accuracy = (logits[row][label] == rowmax)  (exact float equality).
// Row loads are issued FIRST so the dtype-probe ballot and the label load
// resolve under the row-load latency instead of serializing ahead of it.
__global__ __launch_bounds__(256)
void ecce_main_kernel(const float* __restrict__ logits,
                      const void* __restrict__ labels,
                      int N, int C) {
    int warp = (blockIdx.x * blockDim.x + threadIdx.x) >> 5;
    int lane = threadIdx.x & 31;
    if (warp >= N) return;

    const float* row_f = logits + (size_t)warp * C;
    const float4* row = reinterpret_cast<const float4*>(row_f);
    const int nvec = C >> 2;

    float m = -FLT_MAX;
    float s = 0.0f;
    int lab = 0;

    if (nvec == 250) {
        // ---- 1) front-batch 8x LDG.128 per lane: issue before anything else
        const float4 pad = make_float4(-FLT_MAX, -FLT_MAX, -FLT_MAX, -FLT_MAX);
        float4 v[8];
        #pragma unroll
        for (int k = 0; k < 8; k++) {
            int i = lane + (k << 5);
            v[k] = (i < 250) ? row[i] : pad;
        }

        // ---- 2) dtype probe + label load: overlap the row-load latency ----
        // int64 labels in [0,1000) have all-zero high 32-bit words; int32
        // "high words" are other labels — all-zero prob = (1/1000)^32.
        int nprobe = min(32, N >> 1);
        int nz = 0;
        if (lane < nprobe) nz = ((const int*)labels)[2 * lane + 1];
        unsigned any = __ballot_sync(0xFFFFFFFFu, nz != 0);
        if (lane == 0) {
            if (any == 0) lab = (int)((const long long*)labels)[warp];
            else          lab = ((const int*)labels)[warp];
            lab = min(max(lab, 0), NUM_CLS - 1);  // defensive
        }

        // ---- 3) lane-local max: pure FMNMX tree (no index, no predicates)
        #pragma unroll
        for (int k = 0; k < 8; k++)
            m = fmaxf(m, fmaxf(fmaxf(v[k].x, v[k].y), fmaxf(v[k].z, v[k].w)));
        // ---- 4) un-rescaled exp-sum vs lane-local max (pads -> exp(-inf)=0)
        #pragma unroll
        for (int k = 0; k < 8; k++) {
            s += __expf(v[k].x - m) + __expf(v[k].y - m)
               + __expf(v[k].z - m) + __expf(v[k].w - m);
        }
    } else {
        // ---- generic fallback: probe, then online max+sum (no index) ----
        int nprobe = min(32, N >> 1);
        int nz = 0;
        if (lane < nprobe) nz = ((const int*)labels)[2 * lane + 1];
        unsigned any = __ballot_sync(0xFFFFFFFFu, nz != 0);
        if (lane == 0) {
            if (any == 0) lab = (int)((const long long*)labels)[warp];
            else          lab = ((const int*)labels)[warp];
            lab = min(max(lab, 0), NUM_CLS - 1);
        }
        for (int i = lane; i < nvec; i += 32) {
            float4 v = row[i];
            #pragma unroll
            for (int e = 0; e < 4; e++) {
                float x = (e == 0) ? v.x : (e == 1) ? v.y : (e == 2) ? v.z : v.w;
                if (x > m) {
                    s = s * __expf(m - x) + 1.0f;
                    m = x;
                } else {
                    s += __expf(x - m);
                }
            }
        }
    }

    // Warp merge of (m, s): max + rescaled sum.
    #pragma unroll
    for (int off = 16; off > 0; off >>= 1) {
        float m2 = __shfl_down_sync(0xFFFFFFFFu, m, off);
        float s2 = __shfl_down_sync(0xFFFFFFFFu, s, off);
        float mn = fmaxf(m, m2);
        s = s * __expf(m - mn) + s2 * __expf(m2 - mn);
        m = mn;
    }

    if (lane == 0) {
        float conf = 1.0f / s;             // = exp(max-max)/sum(exp(l-max))
        int bin = (int)ceilf(conf * (float)N_BINS) - 1;
        bin = min(max(bin, 0), N_BINS - 1);
        float x_lab = row_f[lab];          // L1-hot: row was just streamed
        float acc = (x_lab == m) ? 1.0f : 0.0f;
        atomicAdd(&g_seg[lab * N_BINS + bin], conf - acc);
    }
}

// Single-block reduction: ecce = sum(|seg|) / N, and re-zero g_seg for the
// next graph replay. 256 threads (small CTA co-schedules earlier under PDL),
// 15 float4 per thread (MLP-rich). cudaGridDependencySynchronize() guarantees
// main's atomics are complete and visible before g_seg is read.
__global__ __launch_bounds__(256)
void ecce_reduce_kernel(float* __restrict__ out, int N) {
    cudaGridDependencySynchronize();       // wait for main grid completion

    __shared__ float sh[8];
    float4* p = reinterpret_cast<float4*>(g_seg);
    const float4 zero4 = make_float4(0.f, 0.f, 0.f, 0.f);

    float acc = 0.0f;
    #pragma unroll 4
    for (int i = threadIdx.x; i < NUM_SEG / 4; i += 256) {
        float4 v = p[i];
        acc += fabsf(v.x) + fabsf(v.y) + fabsf(v.z) + fabsf(v.w);
        p[i] = zero4;  // restore zero invariant
    }

    #pragma unroll
    for (int off = 16; off > 0; off >>= 1)
        acc += __shfl_xor_sync(0xFFFFFFFFu, acc, off);
    int wid = threadIdx.x >> 5, lane = threadIdx.x & 31;
    if (lane == 0) sh[wid] = acc;
    __syncthreads();
    if (threadIdx.x == 0) {
        float t = 0.0f;
        #pragma unroll
        for (int w = 0; w < 8; w++) t += sh[w];
        out[0] = t / (float)N;
    }
}

extern "C" void kernel_launch(void* const* d_in, const int* in_sizes, int n_in,
                              void* d_out, int out_size) {
    // Logits is the (much) larger input; don't assume ordering.
    int i_logits = (in_sizes[0] >= in_sizes[1]) ? 0 : 1;
    int i_labels = 1 - i_logits;

    const float* logits = (const float*)d_in[i_logits];
    const void*  labels = d_in[i_labels];
    float*       out    = (float*)d_out;

    int N = in_sizes[i_labels];           // 131072
    int C = in_sizes[i_logits] / N;       // 1000

    int warps_per_block = 256 / 32;       // 8 rows per block
    int blocks = (N + warps_per_block - 1) / warps_per_block;
    ecce_main_kernel<<<blocks, 256>>>(logits, labels, N, C);

    // PDL launch of the reduce: overlap its launch with main's tail.
    cudaLaunchConfig_t cfg = {};
    cfg.gridDim  = dim3(1, 1, 1);
    cfg.blockDim = dim3(256, 1, 1);
    cfg.dynamicSmemBytes = 0;
    cfg.stream = 0;  // legacy default stream (the capture stream)
    cudaLaunchAttribute attrs[1];
    attrs[0].id = cudaLaunchAttributeProgrammaticStreamSerialization;
    attrs[0].val.programmaticStreamSerializationAllowed = 1;
    cfg.attrs = attrs;
    cfg.numAttrs = 1;
    cudaLaunchKernelEx(&cfg, ecce_reduce_kernel, out, N);
}

// round 13
// speedup vs baseline: 1.3784x; 1.0175x over previous
#include <cuda_runtime.h>
#include <cuda_bf16.h>
#include <float.h>

#define N_BINS 15
#define NUM_CLS 1000
#define NUM_SEG (NUM_CLS * N_BINS)   // 15000, divisible by 4
#define RED_BLOCKS 15                // 15 * 256 threads = 3840 >= 3750 float4

// Scratch: per-(class,bin) signed accumulation of (conf - acc).
// Zero-initialized at module load; the reduce grid re-zeroes it after
// consuming it, so every graph replay starts from zeros.
__device__ float g_seg[NUM_SEG];
__device__ float g_total;            // |.|-sum accumulator (reset by last block)
__device__ unsigned int g_ticket;    // reduce-grid arrival ticket

// One warp per row, no argmax index tracking:
//   accuracy = (logits[row][label] == rowmax)  (exact float equality).
// Row loads are issued FIRST so the dtype-probe ballot and the label load
// resolve under the row-load latency instead of serializing ahead of it.
__global__ __launch_bounds__(256)
void ecce_main_kernel(const float* __restrict__ logits,
                      const void* __restrict__ labels,
                      int N, int C) {
    int warp = (blockIdx.x * blockDim.x + threadIdx.x) >> 5;
    int lane = threadIdx.x & 31;
    if (warp >= N) return;

    const float* row_f = logits + (size_t)warp * C;
    const float4* row = reinterpret_cast<const float4*>(row_f);
    const int nvec = C >> 2;

    float m = -FLT_MAX;
    float s = 0.0f;
    int lab = 0;

    if (nvec == 250) {
        // ---- 1) front-batch 8x LDG.128 per lane: issue before anything else
        const float4 pad = make_float4(-FLT_MAX, -FLT_MAX, -FLT_MAX, -FLT_MAX);
        float4 v[8];
        #pragma unroll
        for (int k = 0; k < 8; k++) {
            int i = lane + (k << 5);
            v[k] = (i < 250) ? row[i] : pad;
        }

        // ---- 2) dtype probe + label load: overlap the row-load latency ----
        // int64 labels in [0,1000) have all-zero high 32-bit words; int32
        // "high words" are other labels — all-zero prob = (1/1000)^32.
        int nprobe = min(32, N >> 1);
        int nz = 0;
        if (lane < nprobe) nz = ((const int*)labels)[2 * lane + 1];
        unsigned any = __ballot_sync(0xFFFFFFFFu, nz != 0);
        if (lane == 0) {
            if (any == 0) lab = (int)((const long long*)labels)[warp];
            else          lab = ((const int*)labels)[warp];
            lab = min(max(lab, 0), NUM_CLS - 1);  // defensive
        }

        // ---- 3) lane-local max: pure FMNMX tree (no index, no predicates)
        #pragma unroll
        for (int k = 0; k < 8; k++)
            m = fmaxf(m, fmaxf(fmaxf(v[k].x, v[k].y), fmaxf(v[k].z, v[k].w)));
        // ---- 4) un-rescaled exp-sum vs lane-local max (pads -> exp(-inf)=0)
        #pragma unroll
        for (int k = 0; k < 8; k++) {
            s += __expf(v[k].x - m) + __expf(v[k].y - m)
               + __expf(v[k].z - m) + __expf(v[k].w - m);
        }
    } else {
        // ---- generic fallback: probe, then online max+sum (no index) ----
        int nprobe = min(32, N >> 1);
        int nz = 0;
        if (lane < nprobe) nz = ((const int*)labels)[2 * lane + 1];
        unsigned any = __ballot_sync(0xFFFFFFFFu, nz != 0);
        if (lane == 0) {
            if (any == 0) lab = (int)((const long long*)labels)[warp];
            else          lab = ((const int*)labels)[warp];
            lab = min(max(lab, 0), NUM_CLS - 1);
        }
        for (int i = lane; i < nvec; i += 32) {
            float4 v = row[i];
            #pragma unroll
            for (int e = 0; e < 4; e++) {
                float x = (e == 0) ? v.x : (e == 1) ? v.y : (e == 2) ? v.z : v.w;
                if (x > m) {
                    s = s * __expf(m - x) + 1.0f;
                    m = x;
                } else {
                    s += __expf(x - m);
                }
            }
        }
    }

    // Warp merge of (m, s): max + rescaled sum.
    #pragma unroll
    for (int off = 16; off > 0; off >>= 1) {
        float m2 = __shfl_down_sync(0xFFFFFFFFu, m, off);
        float s2 = __shfl_down_sync(0xFFFFFFFFu, s, off);
        float mn = fmaxf(m, m2);
        s = s * __expf(m - mn) + s2 * __expf(m2 - mn);
        m = mn;
    }

    if (lane == 0) {
        float conf = 1.0f / s;             // = exp(max-max)/sum(exp(l-max))
        int bin = (int)ceilf(conf * (float)N_BINS) - 1;
        bin = min(max(bin, 0), N_BINS - 1);
        float x_lab = row_f[lab];          // L1-hot: row was just streamed
        float acc = (x_lab == m) ? 1.0f : 0.0f;
        atomicAdd(&g_seg[lab * N_BINS + bin], conf - acc);
    }
}

// Parallel reduction under PDL: 15 blocks x 256 threads, ~1 float4 per
// thread -> ONE parallel L2 round-trip instead of 15 serial ones. Each block
// accumulates |.| over its slice, atomicAdds into g_total, re-zeroes its
// slice; the last-arriving block writes out and resets scratch invariants.
__global__ __launch_bounds__(256)
void ecce_reduce_kernel(float* __restrict__ out, int N) {
    cudaGridDependencySynchronize();       // wait for main grid completion

    __shared__ float sh[8];
    __shared__ unsigned int s_is_last;
    float4* p = reinterpret_cast<float4*>(g_seg);
    const float4 zero4 = make_float4(0.f, 0.f, 0.f, 0.f);

    int i = blockIdx.x * 256 + threadIdx.x;     // < 3840; valid if < 3750
    float acc = 0.0f;
    if (i < NUM_SEG / 4) {
        float4 v = p[i];
        acc = fabsf(v.x) + fabsf(v.y) + fabsf(v.z) + fabsf(v.w);
        p[i] = zero4;                      // restore zero invariant
    }

    #pragma unroll
    for (int off = 16; off > 0; off >>= 1)
        acc += __shfl_xor_sync(0xFFFFFFFFu, acc, off);
    int wid = threadIdx.x >> 5, lane = threadIdx.x & 31;
    if (lane == 0) sh[wid] = acc;
    __syncthreads();

    if (threadIdx.x == 0) {
        float t = 0.0f;
        #pragma unroll
        for (int w = 0; w < 8; w++) t += sh[w];
        atomicAdd(&g_total, t);
        __threadfence();                   // publish g_total + slice zeroing
        unsigned int ticket = atomicAdd(&g_ticket, 1u);
        s_is_last = (ticket == gridDim.x - 1) ? 1u : 0u;
    }
    __syncthreads();
    if (s_is_last && threadIdx.x == 0) {
        __threadfence();                   // acquire all partial adds
        out[0] = g_total / (float)N;
        g_total  = 0.0f;                   // restore invariants for replay
        g_ticket = 0u;
    }
}

extern "C" void kernel_launch(void* const* d_in, const int* in_sizes, int n_in,
                              void* d_out, int out_size) {
    // Logits is the (much) larger input; don't assume ordering.
    int i_logits = (in_sizes[0] >= in_sizes[1]) ? 0 : 1;
    int i_labels = 1 - i_logits;

    const float* logits = (const float*)d_in[i_logits];
    const void*  labels = d_in[i_labels];
    float*       out    = (float*)d_out;

    int N = in_sizes[i_labels];           // 131072
    int C = in_sizes[i_logits] / N;       // 1000

    int warps_per_block = 256 / 32;       // 8 rows per block
    int blocks = (N + warps_per_block - 1) / warps_per_block;
    ecce_main_kernel<<<blocks, 256>>>(logits, labels, N, C);

    // PDL launch of the parallel reduce: overlaps its launch with main's tail.
    cudaLaunchConfig_t cfg = {};
    cfg.gridDim  = dim3(RED_BLOCKS, 1, 1);
    cfg.blockDim = dim3(256, 1, 1);
    cfg.dynamicSmemBytes = 0;
    cfg.stream = 0;  // legacy default stream (the capture stream)
    cudaLaunchAttribute attrs[1];
    attrs[0].id = cudaLaunchAttributeProgrammaticStreamSerialization;
    attrs[0].val.programmaticStreamSerializationAllowed = 1;
    cfg.attrs = attrs;
    cfg.numAttrs = 1;
    cudaLaunchKernelEx(&cfg, ecce_reduce_kernel, out, N);
}

// round 14
// speedup vs baseline: 1.4149x; 1.0265x over previous
#include <cuda_runtime.h>
#include <cuda_bf16.h>
#include <float.h>

#define N_BINS 15
#define NUM_CLS 1000
#define NUM_SEG (NUM_CLS * N_BINS)   // 15000, divisible by 4
#define RED_BLOCKS 15                // 15 * 256 threads = 3840 >= 3750 float4

// Scratch: per-(class,bin) signed accumulation of (conf - acc).
// Zero-initialized at module load; the reduce grid re-zeroes it after
// consuming it, so every graph replay starts from zeros.
__device__ float g_seg[NUM_SEG];
__device__ float g_total;            // |.|-sum accumulator (reset by last block)
__device__ unsigned int g_ticket;    // reduce-grid arrival ticket

__device__ __forceinline__ float ex2f(float x) {
    float y;
    asm("ex2.approx.ftz.f32 %0, %1;" : "=f"(y) : "f"(x));
    return y;
}

// One warp per row, no argmax index tracking:
//   accuracy = (logits[row][label] == rowmax)  (exact float equality).
// Row loads issue FIRST (7 of 8 provably in-bounds -> no pad selects);
// the dtype probe + label + x_lab loads resolve under row-load latency.
// Exp phase runs in the EX2 domain: one FMA + MUFU per element.
__global__ __launch_bounds__(256)
void ecce_main_kernel(const float* __restrict__ logits,
                      const void* __restrict__ labels,
                      int N, int C) {
    int warp = (blockIdx.x * blockDim.x + threadIdx.x) >> 5;
    int lane = threadIdx.x & 31;
    if (warp >= N) return;

    const float* row_f = logits + (size_t)warp * C;
    const float4* row = reinterpret_cast<const float4*>(row_f);
    const int nvec = C >> 2;
    const float L2E = 1.4426950408889634f;

    float m = -FLT_MAX;
    float s = 0.0f;
    int lab = 0;

    if (nvec == 250) {
        // ---- 1) front-batch 8x LDG.128 per lane ----
        // k = 0..6: i = lane + 32k <= 223 < 250, provably in bounds.
        float4 v[8];
        #pragma unroll
        for (int k = 0; k < 7; k++)
            v[k] = row[lane + (k << 5)];
        // k = 7: i = 224 + lane, valid only for lane < 26.
        v[7] = (lane < 26) ? row[224 + lane]
                           : make_float4(-FLT_MAX, -FLT_MAX, -FLT_MAX, -FLT_MAX);

        // ---- 2) dtype probe + label + x_lab: overlap row-load latency ----
        // int64 labels in [0,1000) have all-zero high 32-bit words; int32
        // "high words" are other labels — all-zero prob = (1/1000)^32.
        int nprobe = min(32, N >> 1);
        int nz = 0;
        if (lane < nprobe) nz = ((const int*)labels)[2 * lane + 1];
        unsigned any = __ballot_sync(0xFFFFFFFFu, nz != 0);
        float x_lab = 0.0f;
        if (lane == 0) {
            if (any == 0) lab = (int)((const long long*)labels)[warp];
            else          lab = ((const int*)labels)[warp];
            lab = min(max(lab, 0), NUM_CLS - 1);  // defensive
            x_lab = row_f[lab];                   // issue early; hides under compute
        }

        // ---- 3) lane-local max: pure FMNMX tree ----
        #pragma unroll
        for (int k = 0; k < 8; k++)
            m = fmaxf(m, fmaxf(fmaxf(v[k].x, v[k].y), fmaxf(v[k].z, v[k].w)));

        // ---- 4) exp-sum in EX2 domain: FMA + MUFU per element ----
        float mb = m * L2E;
        #pragma unroll
        for (int k = 0; k < 8; k++) {
            s += ex2f(fmaf(v[k].x, L2E, -mb)) + ex2f(fmaf(v[k].y, L2E, -mb))
               + ex2f(fmaf(v[k].z, L2E, -mb)) + ex2f(fmaf(v[k].w, L2E, -mb));
        }

        // Warp merge of (m, s): max + rescaled sum.
        #pragma unroll
        for (int off = 16; off > 0; off >>= 1) {
            float m2 = __shfl_down_sync(0xFFFFFFFFu, m, off);
            float s2 = __shfl_down_sync(0xFFFFFFFFu, s, off);
            float mn = fmaxf(m, m2);
            s = s * __expf(m - mn) + s2 * __expf(m2 - mn);
            m = mn;
        }

        if (lane == 0) {
            float conf = 1.0f / s;             // = exp(max-max)/sum(exp(l-max))
            int bin = (int)ceilf(conf * (float)N_BINS) - 1;
            bin = min(max(bin, 0), N_BINS - 1);
            float acc = (x_lab == m) ? 1.0f : 0.0f;
            atomicAdd(&g_seg[lab * N_BINS + bin], conf - acc);
        }
    } else {
        // ---- generic fallback: probe, then online max+sum (no index) ----
        int nprobe = min(32, N >> 1);
        int nz = 0;
        if (lane < nprobe) nz = ((const int*)labels)[2 * lane + 1];
        unsigned any = __ballot_sync(0xFFFFFFFFu, nz != 0);
        if (lane == 0) {
            if (any == 0) lab = (int)((const long long*)labels)[warp];
            else          lab = ((const int*)labels)[warp];
            lab = min(max(lab, 0), NUM_CLS - 1);
        }
        for (int i = lane; i < nvec; i += 32) {
            float4 v = row[i];
            #pragma unroll
            for (int e = 0; e < 4; e++) {
                float x = (e == 0) ? v.x : (e == 1) ? v.y : (e == 2) ? v.z : v.w;
                if (x > m) {
                    s = s * __expf(m - x) + 1.0f;
                    m = x;
                } else {
                    s += __expf(x - m);
                }
            }
        }
        #pragma unroll
        for (int off = 16; off > 0; off >>= 1) {
            float m2 = __shfl_down_sync(0xFFFFFFFFu, m, off);
            float s2 = __shfl_down_sync(0xFFFFFFFFu, s, off);
            float mn = fmaxf(m, m2);
            s = s * __expf(m - mn) + s2 * __expf(m2 - mn);
            m = mn;
        }
        if (lane == 0) {
            float conf = 1.0f / s;
            int bin = (int)ceilf(conf * (float)N_BINS) - 1;
            bin = min(max(bin, 0), N_BINS - 1);
            float x_lab = row_f[lab];
            float acc = (x_lab == m) ? 1.0f : 0.0f;
            atomicAdd(&g_seg[lab * N_BINS + bin], conf - acc);
        }
    }
}

// Parallel reduction under PDL: 15 blocks x 256 threads, ~1 float4 per
// thread -> ONE parallel L2 round-trip. Each block accumulates |.| over its
// slice, atomicAdds into g_total, re-zeroes its slice; the last-arriving
// block writes out and resets scratch invariants for the next graph replay.
__global__ __launch_bounds__(256)
void ecce_reduce_kernel(float* __restrict__ out, int N) {
    cudaGridDependencySynchronize();       // wait for main grid completion

    __shared__ float sh[8];
    __shared__ unsigned int s_is_last;
    float4* p = reinterpret_cast<float4*>(g_seg);
    const float4 zero4 = make_float4(0.f, 0.f, 0.f, 0.f);

    int i = blockIdx.x * 256 + threadIdx.x;     // < 3840; valid if < 3750
    float acc = 0.0f;
    if (i < NUM_SEG / 4) {
        float4 v = p[i];
        acc = fabsf(v.x) + fabsf(v.y) + fabsf(v.z) + fabsf(v.w);
        p[i] = zero4;                      // restore zero invariant
    }

    #pragma unroll
    for (int off = 16; off > 0; off >>= 1)
        acc += __shfl_xor_sync(0xFFFFFFFFu, acc, off);
    int wid = threadIdx.x >> 5, lane = threadIdx.x & 31;
    if (lane == 0) sh[wid] = acc;
    __syncthreads();

    if (threadIdx.x == 0) {
        float t = 0.0f;
        #pragma unroll
        for (int w = 0; w < 8; w++) t += sh[w];
        atomicAdd(&g_total, t);
        __threadfence();                   // publish g_total + slice zeroing
        unsigned int ticket = atomicAdd(&g_ticket, 1u);
        s_is_last = (ticket == gridDim.x - 1) ? 1u : 0u;
    }
    __syncthreads();
    if (s_is_last && threadIdx.x == 0) {
        __threadfence();                   // acquire all partial adds
        out[0] = g_total / (float)N;
        g_total  = 0.0f;                   // restore invariants for replay
        g_ticket = 0u;
    }
}

extern "C" void kernel_launch(void* const* d_in, const int* in_sizes, int n_in,
                              void* d_out, int out_size) {
    // Logits is the (much) larger input; don't assume ordering.
    int i_logits = (in_sizes[0] >= in_sizes[1]) ? 0 : 1;
    int i_labels = 1 - i_logits;

    const float* logits = (const float*)d_in[i_logits];
    const void*  labels = d_in[i_labels];
    float*       out    = (float*)d_out;

    int N = in_sizes[i_labels];           // 131072
    int C = in_sizes[i_logits] / N;       // 1000

    int warps_per_block = 256 / 32;       // 8 rows per block
    int blocks = (N + warps_per_block - 1) / warps_per_block;
    ecce_main_kernel<<<blocks, 256>>>(logits, labels, N, C);

    // PDL launch of the parallel reduce: overlaps its launch with main's tail.
    cudaLaunchConfig_t cfg = {};
    cfg.gridDim  = dim3(RED_BLOCKS, 1, 1);
    cfg.blockDim = dim3(256, 1, 1);
    cfg.dynamicSmemBytes = 0;
    cfg.stream = 0;  // legacy default stream (the capture stream)
    cudaLaunchAttribute attrs[1];
    attrs[0].id = cudaLaunchAttributeProgrammaticStreamSerialization;
    attrs[0].val.programmaticStreamSerializationAllowed = 1;
    cfg.attrs = attrs;
    cfg.numAttrs = 1;
    cudaLaunchKernelEx(&cfg, ecce_reduce_kernel, out, N);
}